// round 11
// baseline (speedup 1.0000x reference)
#include <cuda_runtime.h>

// GAE backward scan, (B=8192, T=256, A=4), fp32.
//   c_t = gamma*lambda*nd_t ; d_t = r_t + gamma*nv_t*nd_t - v_t
//   gae_t = d_t + c_t*gae_{t+1}  (gae_T = 0);  adv = gae, ret = gae + v.
// Output: [adv (B*T*A) | ret (B*T*A)].
//
// R11: Blackwell 256-bit loads/stores (ld/st.global.v8.f32). Each lane owns
//      TWO adjacent t-steps per round -> 4 rounds of 64 steps. Local 2-step
//      affine composition + 5-step shuffle scan + 2-shfl exclusive fixup.
//      Halves memory instructions and shfl work per byte vs R5.

#define GAMMA_F 0.99f
#define GL_F    (0.99f * 0.95f)

constexpr int B     = 8192;
constexpr int T     = 256;
constexpr int A     = 4;
constexpr int ROW8  = T * A / 8;    // 128 float8 per batch row
constexpr int WPB   = 4;            // independent warps per block
constexpr int THREADS = 32 * WPB;
constexpr int ROUNDS  = T / 64;     // 4 rounds of 64 t-steps

struct f8 { float4 lo, hi; };       // lo = t-step 2l (agents 0..3), hi = 2l+1

__device__ __forceinline__ f8 ldg256(const float* p) {
    f8 v;
    asm volatile("ld.global.v8.f32 {%0,%1,%2,%3,%4,%5,%6,%7}, [%8];"
                 : "=f"(v.lo.x), "=f"(v.lo.y), "=f"(v.lo.z), "=f"(v.lo.w),
                   "=f"(v.hi.x), "=f"(v.hi.y), "=f"(v.hi.z), "=f"(v.hi.w)
                 : "l"(p));
    return v;
}

__device__ __forceinline__ void stg256(float* p, const f8 v) {
    asm volatile("st.global.v8.f32 [%0], {%1,%2,%3,%4,%5,%6,%7,%8};"
                 :: "l"(p),
                    "f"(v.lo.x), "f"(v.lo.y), "f"(v.lo.z), "f"(v.lo.w),
                    "f"(v.hi.x), "f"(v.hi.y), "f"(v.hi.z), "f"(v.hi.w)
                 : "memory");
}

struct Chunk { f8 r, tm, v, nv; };

__device__ __forceinline__ Chunk ld_round(const float* __restrict__ reward,
                                          const float* __restrict__ term,
                                          const float* __restrict__ value,
                                          const float* __restrict__ nxtval,
                                          long g8)
{
    const long off = g8 * 8;
    Chunk c;
    c.r  = ldg256(reward + off);
    c.tm = ldg256(term   + off);
    c.v  = ldg256(value  + off);
    c.nv = ldg256(nxtval + off);
    return c;
}

__global__ __launch_bounds__(THREADS)
void gae_kernel(const float* __restrict__ reward,
                const float* __restrict__ term,
                const float* __restrict__ value,
                const float* __restrict__ nxtval,
                float* __restrict__ adv_out,
                float* __restrict__ ret_out)
{
    const int lane = threadIdx.x & 31;
    const int warp = threadIdx.x >> 5;
    const int b    = blockIdx.x * WPB + warp;
    const long base8 = (long)b * ROW8 + lane;   // lane's float8 slot in round 0

    float carry[4] = {0.f, 0.f, 0.f, 0.f};

    // depth-2 prologue: rounds 3 and 2 both in flight
    Chunk buf[2];
    buf[(ROUNDS - 1) & 1] = ld_round(reward, term, value, nxtval,
                                     base8 + 32 * (ROUNDS - 1));
    buf[(ROUNDS - 2) & 1] = ld_round(reward, term, value, nxtval,
                                     base8 + 32 * (ROUNDS - 2));

    #pragma unroll
    for (int k = ROUNDS - 1; k >= 0; k--) {
        const int s = k & 1;
        const Chunk cur = buf[s];

        // refill this slot two rounds ahead; latency overlaps two scans
        if (k >= 2)
            buf[s] = ld_round(reward, term, value, nxtval, base8 + 32 * (k - 2));

        const float* rlo = &cur.r.lo.x;  const float* rhi = &cur.r.hi.x;
        const float* tlo = &cur.tm.lo.x; const float* thi = &cur.tm.hi.x;
        const float* vlo = &cur.v.lo.x;  const float* vhi = &cur.v.hi.x;
        const float* nlo = &cur.nv.lo.x; const float* nhi = &cur.nv.hi.x;

        f8 ad, rt;
        float* adlo = &ad.lo.x;  float* adhi = &ad.hi.x;
        float* rtlo = &rt.lo.x;  float* rthi = &rt.hi.x;

        #pragma unroll
        for (int j = 0; j < 4; j++) {
            // local 2-step segment: t_even (lo) then t_odd (hi)
            const float nd0 = 1.0f - tlo[j];
            const float nd1 = 1.0f - thi[j];
            const float c0  = GL_F * nd0;
            const float c1  = GL_F * nd1;
            const float d0  = fmaf(GAMMA_F * nlo[j], nd0, rlo[j]) - vlo[j];
            const float d1  = fmaf(GAMMA_F * nhi[j], nd1, rhi[j]) - vhi[j];

            float Sc  = c0 * c1;           // segment scale
            float Off = fmaf(c0, d1, d0);  // segment offset

            // backward inclusive affine scan over lanes (segments l..31)
            #pragma unroll
            for (int off = 1; off < 32; off <<= 1) {
                const float ScU  = __shfl_down_sync(0xffffffffu, Sc,  off);
                const float OffU = __shfl_down_sync(0xffffffffu, Off, off);
                if (lane + off < 32) {
                    Off = fmaf(Sc, OffU, Off);
                    Sc *= ScU;
                }
            }

            // exclusive value for the odd step: gae entering segment l+1
            const float Sn = __shfl_down_sync(0xffffffffu, Sc,  1);
            const float On = __shfl_down_sync(0xffffffffu, Off, 1);
            const float gin = (lane < 31) ? fmaf(Sn, carry[j], On) : carry[j];

            const float ge = fmaf(Sc, carry[j], Off);  // gae at t = 64k+2l
            const float go = fmaf(c1, gin, d1);        // gae at t = 64k+2l+1

            carry[j] = __shfl_sync(0xffffffffu, ge, 0);  // gae at t = 64k

            adlo[j] = ge;             adhi[j] = go;
            rtlo[j] = ge + vlo[j];    rthi[j] = go + vhi[j];
        }

        const long off = (base8 + 32 * k) * 8;
        stg256(adv_out + off, ad);
        stg256(ret_out + off, rt);
    }
}

extern "C" void kernel_launch(void* const* d_in, const int* in_sizes, int n_in,
                              void* d_out, int out_size)
{
    const float* reward = (const float*)d_in[0];
    const float* term   = (const float*)d_in[1];
    const float* value  = (const float*)d_in[2];
    const float* nxtval = (const float*)d_in[3];

    float* out = (float*)d_out;
    float* adv = out;
    float* ret = out + (size_t)B * T * A;

    gae_kernel<<<B / WPB, THREADS>>>(reward, term, value, nxtval, adv, ret);
}

// round 12
// speedup vs baseline: 1.0077x; 1.0077x over previous
#include <cuda_runtime.h>

// GAE backward scan, (B=8192, T=256, A=4), fp32.
//   c_t = gamma*lambda*nd_t ; d_t = r_t + gamma*nv_t*nd_t - v_t
//   gae_t = d_t + c_t*gae_{t+1}  (gae_T = 0);  adv = gae, ret = gae + v.
// Output: [adv (B*T*A) | ret (B*T*A)].
//
// R12: R11 (256-bit v8 loads/stores, 2 t-steps per lane, 4 rounds) with
//      streaming cache qualifiers (.cs) on both the v8 loads and stores —
//      merging R5's best cache policy with R11's minimal instruction count.
//      Warp affine scan, depth-2 register pipeline, no smem, no barriers.

#define GAMMA_F 0.99f
#define GL_F    (0.99f * 0.95f)

constexpr int B     = 8192;
constexpr int T     = 256;
constexpr int A     = 4;
constexpr int ROW8  = T * A / 8;    // 128 float8 per batch row
constexpr int WPB   = 4;            // independent warps per block
constexpr int THREADS = 32 * WPB;
constexpr int ROUNDS  = T / 64;     // 4 rounds of 64 t-steps

struct f8 { float4 lo, hi; };       // lo = t-step 2l (agents 0..3), hi = 2l+1

__device__ __forceinline__ f8 ldg256cs(const float* p) {
    f8 v;
    asm volatile("ld.global.cs.v8.f32 {%0,%1,%2,%3,%4,%5,%6,%7}, [%8];"
                 : "=f"(v.lo.x), "=f"(v.lo.y), "=f"(v.lo.z), "=f"(v.lo.w),
                   "=f"(v.hi.x), "=f"(v.hi.y), "=f"(v.hi.z), "=f"(v.hi.w)
                 : "l"(p));
    return v;
}

__device__ __forceinline__ void stg256cs(float* p, const f8 v) {
    asm volatile("st.global.cs.v8.f32 [%0], {%1,%2,%3,%4,%5,%6,%7,%8};"
                 :: "l"(p),
                    "f"(v.lo.x), "f"(v.lo.y), "f"(v.lo.z), "f"(v.lo.w),
                    "f"(v.hi.x), "f"(v.hi.y), "f"(v.hi.z), "f"(v.hi.w)
                 : "memory");
}

struct Chunk { f8 r, tm, v, nv; };

__device__ __forceinline__ Chunk ld_round(const float* __restrict__ reward,
                                          const float* __restrict__ term,
                                          const float* __restrict__ value,
                                          const float* __restrict__ nxtval,
                                          long g8)
{
    const long off = g8 * 8;
    Chunk c;
    c.r  = ldg256cs(reward + off);
    c.tm = ldg256cs(term   + off);
    c.v  = ldg256cs(value  + off);
    c.nv = ldg256cs(nxtval + off);
    return c;
}

__global__ __launch_bounds__(THREADS)
void gae_kernel(const float* __restrict__ reward,
                const float* __restrict__ term,
                const float* __restrict__ value,
                const float* __restrict__ nxtval,
                float* __restrict__ adv_out,
                float* __restrict__ ret_out)
{
    const int lane = threadIdx.x & 31;
    const int warp = threadIdx.x >> 5;
    const int b    = blockIdx.x * WPB + warp;
    const long base8 = (long)b * ROW8 + lane;   // lane's float8 slot in round 0

    float carry[4] = {0.f, 0.f, 0.f, 0.f};

    // depth-2 prologue: rounds 3 and 2 both in flight
    Chunk buf[2];
    buf[(ROUNDS - 1) & 1] = ld_round(reward, term, value, nxtval,
                                     base8 + 32 * (ROUNDS - 1));
    buf[(ROUNDS - 2) & 1] = ld_round(reward, term, value, nxtval,
                                     base8 + 32 * (ROUNDS - 2));

    #pragma unroll
    for (int k = ROUNDS - 1; k >= 0; k--) {
        const int s = k & 1;
        const Chunk cur = buf[s];

        // refill this slot two rounds ahead; latency overlaps two scans
        if (k >= 2)
            buf[s] = ld_round(reward, term, value, nxtval, base8 + 32 * (k - 2));

        const float* rlo = &cur.r.lo.x;  const float* rhi = &cur.r.hi.x;
        const float* tlo = &cur.tm.lo.x; const float* thi = &cur.tm.hi.x;
        const float* vlo = &cur.v.lo.x;  const float* vhi = &cur.v.hi.x;
        const float* nlo = &cur.nv.lo.x; const float* nhi = &cur.nv.hi.x;

        f8 ad, rt;
        float* adlo = &ad.lo.x;  float* adhi = &ad.hi.x;
        float* rtlo = &rt.lo.x;  float* rthi = &rt.hi.x;

        #pragma unroll
        for (int j = 0; j < 4; j++) {
            // local 2-step segment: t_even (lo) then t_odd (hi)
            const float nd0 = 1.0f - tlo[j];
            const float nd1 = 1.0f - thi[j];
            const float c0  = GL_F * nd0;
            const float c1  = GL_F * nd1;
            const float d0  = fmaf(GAMMA_F * nlo[j], nd0, rlo[j]) - vlo[j];
            const float d1  = fmaf(GAMMA_F * nhi[j], nd1, rhi[j]) - vhi[j];

            float Sc  = c0 * c1;           // segment scale
            float Off = fmaf(c0, d1, d0);  // segment offset

            // backward inclusive affine scan over lanes (segments l..31)
            #pragma unroll
            for (int off = 1; off < 32; off <<= 1) {
                const float ScU  = __shfl_down_sync(0xffffffffu, Sc,  off);
                const float OffU = __shfl_down_sync(0xffffffffu, Off, off);
                if (lane + off < 32) {
                    Off = fmaf(Sc, OffU, Off);
                    Sc *= ScU;
                }
            }

            // exclusive value for the odd step: gae entering segment l+1
            const float Sn = __shfl_down_sync(0xffffffffu, Sc,  1);
            const float On = __shfl_down_sync(0xffffffffu, Off, 1);
            const float gin = (lane < 31) ? fmaf(Sn, carry[j], On) : carry[j];

            const float ge = fmaf(Sc, carry[j], Off);  // gae at t = 64k+2l
            const float go = fmaf(c1, gin, d1);        // gae at t = 64k+2l+1

            carry[j] = __shfl_sync(0xffffffffu, ge, 0);  // gae at t = 64k

            adlo[j] = ge;             adhi[j] = go;
            rtlo[j] = ge + vlo[j];    rthi[j] = go + vhi[j];
        }

        const long off = (base8 + 32 * k) * 8;
        stg256cs(adv_out + off, ad);
        stg256cs(ret_out + off, rt);
    }
}

extern "C" void kernel_launch(void* const* d_in, const int* in_sizes, int n_in,
                              void* d_out, int out_size)
{
    const float* reward = (const float*)d_in[0];
    const float* term   = (const float*)d_in[1];
    const float* value  = (const float*)d_in[2];
    const float* nxtval = (const float*)d_in[3];

    float* out = (float*)d_out;
    float* adv = out;
    float* ret = out + (size_t)B * T * A;

    gae_kernel<<<B / WPB, THREADS>>>(reward, term, value, nxtval, adv, ret);
}